// round 5
// baseline (speedup 1.0000x reference)
#include <cuda_runtime.h>
#include <cstdint>
#include <math.h>

// Problem constants
#define Bq 16
#define Nq 4096
#define Cq 81
#define MAXPC 4096   // max candidates per (b,c) AND per image (each roi emits <=1 candidate total)
#define KK 200       // per-class cap and final output count
#define NW 7         // ceil(200/32) words for keep/suppress bitmasks
#define SLOWS 512    // smem sort capacity in the slow path

typedef unsigned long long u64;

// ---------------- device scratch (allocation-free rule: __device__ globals) ----------------
// Counters start zeroed (static init) and are re-zeroed by their consumer kernel each run,
// so every graph replay sees clean state without a dedicated zeroing launch.
__device__ int   g_cnt[Bq * Cq];                        // per-(b,c) candidate counts
__device__ float g_cscore[(size_t)Bq * Cq * MAXPC];     // per-(b,c) candidate scores
__device__ int   g_cidx[(size_t)Bq * Cq * MAXPC];       // per-(b,c) candidate roi indices
__device__ int   g_kcnt[Bq];                            // per-image kept counts
__device__ float g_kscore[Bq * MAXPC];
__device__ float g_kbox[Bq * MAXPC * 4];
__device__ int   g_ktag[Bq * MAXPC];                    // tag = class*4096 + roi_idx (<2^19)

// ---------------- kernel 1: direct-global argmax, 4 threads per roi ----------------
// Each thread scans a contiguous quarter of one row (21/21/21/18 elements). A warp covers
// 8 rows = 2592 contiguous bytes, so every 128B line is fully consumed (L1 reuse) and the
// aggregate DRAM traffic is the minimal 21 MB. No smem, no barriers -> max occupancy.
// A softmax score can only exceed 0.5 for its argmax class, and background (argmax==0)
// rois are zeroed by the reference, so each roi emits <=1 candidate.
__global__ void __launch_bounds__(256) argmax_emit_kernel(const float* __restrict__ probs) {
    const unsigned FULL = 0xffffffffu;
    int t = blockIdx.x * blockDim.x + threadIdx.x;
    int g = t >> 2;                 // roi id
    int q = t & 3;                  // quarter within the row
    int lane = threadIdx.x & 31;

    const float* __restrict__ r = probs + (size_t)g * Cq;
    int k0 = q * 21;
    float v = -1.0f; int ix = 0;
    #pragma unroll
    for (int k = 0; k < 21; k++) {
        int idx = k0 + k;
        float pv = (idx < Cq) ? __ldg(r + idx) : -1.0f;
        if (pv > v) { v = pv; ix = idx; }    // strict > keeps lowest index
    }
    // merge the 4 quarters (sources always carry larger indices -> generic tie rule is safe)
    #pragma unroll
    for (int off = 2; off; off >>= 1) {
        float ov = __shfl_down_sync(FULL, v, off);
        int   oi = __shfl_down_sync(FULL, ix, off);
        if ((lane & 3) + off < 4 && (ov > v || (ov == v && oi < ix))) { v = ov; ix = oi; }
    }
    if (q == 0 && ix != 0 && v > 0.5f) {
        int b = g >> 12, n = g & (Nq - 1);
        int bc = b * Cq + ix;
        int pos = atomicAdd(&g_cnt[bc], 1);
        if (pos < MAXPC) {
            g_cscore[(size_t)bc * MAXPC + pos] = v;
            g_cidx[(size_t)bc * MAXPC + pos]   = n;
        }
    }
}

// ---------------- kernel 2: per-(b,c) sort + cap-200 + greedy NMS (one warp per block) ----------
__device__ __forceinline__ void decode_box(const float* __restrict__ roi,
                                           const float* __restrict__ deltas,
                                           int b, int c, int idx,
                                           float& oy1, float& ox1, float& oy2, float& ox2) {
    const float* r = roi + ((size_t)b * Nq + idx) * 4;
    float y1 = r[0], x1 = r[1], y2 = r[2], x2 = r[3];
    float ah = y2 - y1, aw = x2 - x1;
    float acy = y1 + 0.5f * ah, acx = x1 + 0.5f * aw;
    const float* d = deltas + (((size_t)b * Nq + idx) * Cq + c) * 4;
    float dy = d[0] * 0.1f, dx = d[1] * 0.1f;
    float dh = d[2] * 0.2f, dw = d[3] * 0.2f;
    float bh = expf(dh) * ah, bw = expf(dw) * aw;
    float bcy = dy * ah + acy, bcx = dx * aw + acx;
    oy1 = bcy - 0.5f * bh; ox1 = bcx - 0.5f * bw;
    oy2 = oy1 + bh;        ox2 = ox1 + bw;
}

__global__ void __launch_bounds__(32) per_class_nms_kernel(const float* __restrict__ roi,
                                                           const float* __restrict__ deltas) {
    __shared__ u64 skey[SLOWS];            // slow path only
    __shared__ float sbox[KK * 4];
    __shared__ unsigned smask[KK * NW];
    __shared__ unsigned skeep[NW];

    const unsigned FULL = 0xffffffffu;
    int bc = blockIdx.x;
    int b = bc / Cq, c = bc % Cq;
    int lane = threadIdx.x;
    int M = g_cnt[bc];                     // all lanes read before lane 0 resets
    if (M > MAXPC) M = MAXPC;
    if (M == 0) return;
    if (lane == 0) g_cnt[bc] = 0;          // reset for next graph replay

    // ======================= FAST PATH: M <= 32, fully warp-resident =======================
    if (M <= 32) {
        u64 key = 0ull;
        if (lane < M) {
            float sc = g_cscore[(size_t)bc * MAXPC + lane];
            int   idx = g_cidx[(size_t)bc * MAXPC + lane];
            key = ((u64)__float_as_uint(sc) << 32) | (unsigned)(Nq - 1 - idx);
        }
        // in-register bitonic sort, descending (padding keys 0 sink to the end)
        #pragma unroll
        for (int k = 2; k <= 32; k <<= 1) {
            #pragma unroll
            for (int j = k >> 1; j > 0; j >>= 1) {
                u64 other = __shfl_xor_sync(FULL, key, j);
                bool up = ((lane & j) == 0);
                bool desc = ((lane & k) == 0);
                u64 mx = key > other ? key : other;
                u64 mn = key > other ? other : key;
                key = (desc == up) ? mx : mn;
            }
        }
        int M2 = M;   // <= 32 <= KK

        float by1 = 0.f, bxx1 = 0.f, by2 = 0.f, bxx2 = 0.f, area = 0.f;
        if (lane < M2) {
            int idx = Nq - 1 - (int)(key & 0xFFFFFFFFull);
            decode_box(roi, deltas, b, c, idx, by1, bxx1, by2, bxx2);
            area = fmaxf(by2 - by1, 0.0f) * fmaxf(bxx2 - bxx1, 0.0f);
        }

        // greedy NMS: shfl-broadcast box i, ballot the suppressions (keep is warp-uniform)
        unsigned keep = (M2 >= 32) ? FULL : ((1u << M2) - 1u);
        for (int i = 0; i < M2 - 1; i++) {
            if ((keep >> i) & 1u) {
                float iy1 = __shfl_sync(FULL, by1, i);
                float ix1 = __shfl_sync(FULL, bxx1, i);
                float iy2 = __shfl_sync(FULL, by2, i);
                float ix2 = __shfl_sync(FULL, bxx2, i);
                float ia  = __shfl_sync(FULL, area, i);
                float yy1 = fmaxf(iy1, by1), xx1 = fmaxf(ix1, bxx1);
                float yy2 = fminf(iy2, by2), xx2 = fminf(ix2, bxx2);
                float inter = fmaxf(yy2 - yy1, 0.0f) * fmaxf(xx2 - xx1, 0.0f);
                float iou = inter / (ia + area - inter + 1e-8f);
                unsigned sup = __ballot_sync(FULL,
                    (lane > i) && (lane < M2) && ((keep >> lane) & 1u) && (iou > 0.5f));
                keep &= ~sup;
            }
        }

        int nk = __popc(keep);
        int base = 0;
        if (lane == 0) base = atomicAdd(&g_kcnt[b], nk);
        base = __shfl_sync(FULL, base, 0);
        if ((lane < M2) && ((keep >> lane) & 1u)) {
            int pos = __popc(keep & ((lane == 0) ? 0u : ((1u << lane) - 1u)));
            int o = base + pos;
            int idx = Nq - 1 - (int)(key & 0xFFFFFFFFull);
            g_kscore[b * MAXPC + o] = __uint_as_float((unsigned)(key >> 32));
            g_ktag[b * MAXPC + o]   = c * Nq + idx;
            g_kbox[(b * MAXPC + o) * 4 + 0] = by1;
            g_kbox[(b * MAXPC + o) * 4 + 1] = bxx1;
            g_kbox[(b * MAXPC + o) * 4 + 2] = by2;
            g_kbox[(b * MAXPC + o) * 4 + 3] = bxx2;
        }
        return;
    }

    // ======================= SLOW PATH: M > 32 (rare; correctness-first) ====================
    int S = 64; while (S < M) S <<= 1;
    bool in_smem = (S <= SLOWS);

    if (in_smem) {
        for (int i = lane; i < S; i += 32) {
            u64 key = 0ull;
            if (i < M) {
                float sc = g_cscore[(size_t)bc * MAXPC + i];
                int   idx = g_cidx[(size_t)bc * MAXPC + i];
                key = ((u64)__float_as_uint(sc) << 32) | (unsigned)(Nq - 1 - idx);
            }
            skey[i] = key;
        }
        __syncwarp();
        for (int k = 2; k <= S; k <<= 1)
            for (int j = k >> 1; j > 0; j >>= 1) {
                for (int i = lane; i < S; i += 32) {
                    int ixj = i ^ j;
                    if (ixj > i) {
                        u64 a = skey[i], bv = skey[ixj];
                        bool sw = ((i & k) == 0) ? (a < bv) : (a > bv);
                        if (sw) { skey[i] = bv; skey[ixj] = a; }
                    }
                }
                __syncwarp();
            }
    } else {
        // pad the global arrays to S (capacity MAXPC), then bitonic-sort them in place
        for (int i = M + lane; i < S; i += 32) {
            g_cscore[(size_t)bc * MAXPC + i] = 0.0f;
            g_cidx[(size_t)bc * MAXPC + i]   = Nq - 1;
        }
        __syncwarp(); __threadfence_block();
        for (int k = 2; k <= S; k <<= 1)
            for (int j = k >> 1; j > 0; j >>= 1) {
                for (int i = lane; i < S; i += 32) {
                    int ixj = i ^ j;
                    if (ixj > i) {
                        float sa = g_cscore[(size_t)bc * MAXPC + i];
                        float sb = g_cscore[(size_t)bc * MAXPC + ixj];
                        int ida = g_cidx[(size_t)bc * MAXPC + i];
                        int idb = g_cidx[(size_t)bc * MAXPC + ixj];
                        u64 a = ((u64)__float_as_uint(sa) << 32) | (unsigned)(Nq - 1 - ida);
                        u64 bv = ((u64)__float_as_uint(sb) << 32) | (unsigned)(Nq - 1 - idb);
                        bool sw = ((i & k) == 0) ? (a < bv) : (a > bv);
                        if (sw) {
                            g_cscore[(size_t)bc * MAXPC + i]   = sb;
                            g_cscore[(size_t)bc * MAXPC + ixj] = sa;
                            g_cidx[(size_t)bc * MAXPC + i]     = idb;
                            g_cidx[(size_t)bc * MAXPC + ixj]   = ida;
                        }
                    }
                }
                __syncwarp(); __threadfence_block();
            }
    }

    int M2 = (M < KK) ? M : KK;

    // decode boxes + zero bitmask
    for (int t = lane; t < M2 * NW; t += 32) smask[t] = 0u;
    for (int t = lane; t < M2; t += 32) {
        int idx;
        float sc;
        if (in_smem) {
            idx = Nq - 1 - (int)(skey[t] & 0xFFFFFFFFull);
            sc  = __uint_as_float((unsigned)(skey[t] >> 32));
        } else {
            idx = g_cidx[(size_t)bc * MAXPC + t];
            sc  = g_cscore[(size_t)bc * MAXPC + t];
        }
        float oy1, ox1, oy2, ox2;
        decode_box(roi, deltas, b, c, idx, oy1, ox1, oy2, ox2);
        sbox[t * 4 + 0] = oy1; sbox[t * 4 + 1] = ox1;
        sbox[t * 4 + 2] = oy2; sbox[t * 4 + 3] = ox2;
        (void)sc;
    }
    __syncwarp();

    // IoU bit-matrix
    int npairs = M2 * M2;
    for (int t = lane; t < npairs; t += 32) {
        int i = t / M2, j = t % M2;
        if (j > i) {
            float iy1 = sbox[i * 4 + 0], ix1 = sbox[i * 4 + 1];
            float iy2 = sbox[i * 4 + 2], ix2 = sbox[i * 4 + 3];
            float jy1 = sbox[j * 4 + 0], jx1 = sbox[j * 4 + 1];
            float jy2 = sbox[j * 4 + 2], jx2 = sbox[j * 4 + 3];
            float yy1 = fmaxf(iy1, jy1), xx1 = fmaxf(ix1, jx1);
            float yy2 = fminf(iy2, jy2), xx2 = fminf(ix2, jx2);
            float inter = fmaxf(yy2 - yy1, 0.0f) * fmaxf(xx2 - xx1, 0.0f);
            float ia = fmaxf(iy2 - iy1, 0.0f) * fmaxf(ix2 - ix1, 0.0f);
            float ja = fmaxf(jy2 - jy1, 0.0f) * fmaxf(jx2 - jx1, 0.0f);
            float iou = inter / (ia + ja - inter + 1e-8f);
            if (iou > 0.5f)
                atomicOr(&smask[i * NW + (j >> 5)], 1u << (j & 31));
        }
    }
    __syncwarp();

    // greedy scan: keep mask in lanes 0..NW-1
    {
        int w = lane;
        unsigned kw = 0u;
        if (w < NW) {
            int lo = w * 32, nb = M2 - lo;
            kw = (nb >= 32) ? 0xFFFFFFFFu : (nb <= 0 ? 0u : ((1u << nb) - 1u));
        }
        for (int i = 0; i < M2; i++) {
            unsigned ow = __shfl_sync(FULL, kw, i >> 5);
            if ((ow >> (i & 31)) & 1u) {
                if (w < NW) kw &= ~smask[i * NW + w];
            }
        }
        if (w < NW) skeep[w] = kw;
    }
    __syncwarp();

    int nk = 0;
    for (int w = 0; w < NW; w++) nk += __popc(skeep[w]);
    int base = 0;
    if (lane == 0) base = atomicAdd(&g_kcnt[b], nk);
    base = __shfl_sync(FULL, base, 0);

    for (int t = lane; t < M2; t += 32) {
        int tw = t >> 5, tb = t & 31;
        if ((skeep[tw] >> tb) & 1u) {
            int pos = 0;
            for (int w = 0; w < tw; w++) pos += __popc(skeep[w]);
            pos += __popc(skeep[tw] & ((tb == 0) ? 0u : ((1u << tb) - 1u)));
            int o = base + pos;
            int idx; float sc;
            if (in_smem) {
                idx = Nq - 1 - (int)(skey[t] & 0xFFFFFFFFull);
                sc  = __uint_as_float((unsigned)(skey[t] >> 32));
            } else {
                idx = g_cidx[(size_t)bc * MAXPC + t];
                sc  = g_cscore[(size_t)bc * MAXPC + t];
            }
            g_kscore[b * MAXPC + o] = sc;
            g_ktag[b * MAXPC + o]   = c * Nq + idx;
            g_kbox[(b * MAXPC + o) * 4 + 0] = sbox[t * 4 + 0];
            g_kbox[(b * MAXPC + o) * 4 + 1] = sbox[t * 4 + 1];
            g_kbox[(b * MAXPC + o) * 4 + 2] = sbox[t * 4 + 2];
            g_kbox[(b * MAXPC + o) * 4 + 3] = sbox[t * 4 + 3];
        }
    }
}

// ---------------- kernel 3: per-image top-200 via radix-bucket select + small sort ----------------
// Scores of survivors are all in (0.5, 1.0) -> fp32 exponent is constant, so mantissa bits
// are monotone in score. 256-bucket histogram finds the 200th-largest's bucket; only keys
// in buckets >= that one are compacted and bitonic-sorted (typically a few hundred, not 4096).
__device__ __forceinline__ int score_bucket(unsigned bits) {
    unsigned d = bits - 0x3F000000u;     // (0, 0x800000] for scores in (0.5, 1.0]
    int bk = (int)(d >> 15);
    return bk > 255 ? 255 : bk;
}

__global__ void finalize_kernel(float* __restrict__ out) {
    __shared__ u64 skey[MAXPC];   // 32 KB (worst case all keys in one bucket)
    __shared__ int hist[256];
    __shared__ int s_cnt, s_bsel;

    int b = blockIdx.x;
    int Mi = g_kcnt[b];
    if (Mi > MAXPC) Mi = MAXPC;

    for (int i = threadIdx.x; i < 256; i += blockDim.x) hist[i] = 0;
    if (threadIdx.x == 0) { s_cnt = 0; g_kcnt[b] = 0; }   // reset for next graph replay
    __syncthreads();

    for (int i = threadIdx.x; i < Mi; i += blockDim.x) {
        unsigned bits = __float_as_uint(g_kscore[b * MAXPC + i]);
        atomicAdd(&hist[score_bucket(bits)], 1);
    }
    __syncthreads();

    if (threadIdx.x == 0) {
        int target = Mi < KK ? Mi : KK;
        int cum = 0, bsel = 0;
        for (int bk = 255; bk >= 0; bk--) {
            cum += hist[bk];
            if (cum >= target) { bsel = bk; break; }
        }
        s_bsel = bsel;
    }
    __syncthreads();
    int bsel = s_bsel;

    // compact candidate keys (score desc; tie -> class asc, roi asc via inverted tag;
    // low 12 bits carry the storage slot as payload)
    for (int i = threadIdx.x; i < Mi; i += blockDim.x) {
        unsigned bits = __float_as_uint(g_kscore[b * MAXPC + i]);
        if (score_bucket(bits) >= bsel) {
            int pos = atomicAdd(&s_cnt, 1);
            int tag = g_ktag[b * MAXPC + i];            // < 2^19
            skey[pos] = ((u64)bits << 32) |
                        ((u64)((0xFFFFFu - (unsigned)tag) & 0xFFFFFu) << 12) |
                        (u64)(unsigned)i;
        }
    }
    __syncthreads();
    int cnt = s_cnt;

    int S = 0;
    if (cnt > 0) { S = 32; while (S < cnt) S <<= 1; }
    for (int i = cnt + threadIdx.x; i < S; i += blockDim.x) skey[i] = 0ull;
    __syncthreads();

    for (int k = 2; k <= S; k <<= 1) {
        for (int j = k >> 1; j > 0; j >>= 1) {
            for (int i = threadIdx.x; i < S; i += blockDim.x) {
                int ixj = i ^ j;
                if (ixj > i) {
                    u64 a = skey[i], bv = skey[ixj];
                    bool sw = ((i & k) == 0) ? (a < bv) : (a > bv);
                    if (sw) { skey[i] = bv; skey[ixj] = a; }
                }
            }
            __syncthreads();
        }
    }

    // write top-200 (boxes, labels, scores), zero-padding: covers 100% of d_out
    int vlim = cnt < KK ? cnt : KK;                 // == min(KK, Mi) since cnt >= min(KK, Mi)
    for (int t = threadIdx.x; t < KK; t += blockDim.x) {
        float bx0 = 0.f, bx1 = 0.f, bx2 = 0.f, bx3 = 0.f, lbl = 0.f, scv = 0.f;
        if (t < vlim) {
            u64 key = skey[t];
            scv = __uint_as_float((unsigned)(key >> 32));   // always > 0.5 here
            int slot = (int)(key & 0xFFFull);
            int tag = 0xFFFFF - (int)((key >> 12) & 0xFFFFFull);
            lbl = (float)(tag >> 12);                       // tag / 4096 = class
            const float* bp = &g_kbox[(b * MAXPC + slot) * 4];
            bx0 = fminf(fmaxf(bp[0], 0.0f), 1.0f);
            bx1 = fminf(fmaxf(bp[1], 0.0f), 1.0f);
            bx2 = fminf(fmaxf(bp[2], 0.0f), 1.0f);
            bx3 = fminf(fmaxf(bp[3], 0.0f), 1.0f);
        }
        float* ob = out + ((size_t)b * KK + t) * 4;
        ob[0] = bx0; ob[1] = bx1; ob[2] = bx2; ob[3] = bx3;
        out[(size_t)Bq * KK * 4 + (size_t)b * KK + t] = lbl;
        out[(size_t)Bq * KK * 4 + (size_t)Bq * KK + (size_t)b * KK + t] = scv;
    }
}

// ---------------- host launch ----------------
extern "C" void kernel_launch(void* const* d_in, const int* in_sizes, int n_in,
                              void* d_out, int out_size) {
    const float* roi = nullptr;     // B*N*4       = 262144
    const float* deltas = nullptr;  // B*N*C*4     = 21233664
    const float* probs = nullptr;   // B*N*C       = 5308416
    for (int i = 0; i < n_in; i++) {
        if (in_sizes[i] == Bq * Nq * 4)           roi    = (const float*)d_in[i];
        else if (in_sizes[i] == Bq * Nq * Cq * 4) deltas = (const float*)d_in[i];
        else if (in_sizes[i] == Bq * Nq * Cq)     probs  = (const float*)d_in[i];
    }
    float* out = (float*)d_out;

    argmax_emit_kernel<<<(Bq * Nq * 4) / 256, 256>>>(probs);
    per_class_nms_kernel<<<Bq * Cq, 32>>>(roi, deltas);
    finalize_kernel<<<Bq, 1024>>>(out);
}

// round 6
// speedup vs baseline: 1.1448x; 1.1448x over previous
#include <cuda_runtime.h>
#include <cstdint>
#include <math.h>

// Problem constants
#define Bq 16
#define Nq 4096
#define Cq 81
#define MAXPC 4096   // max candidates per (b,c) AND per image (each roi emits <=1 candidate total)
#define KK 200       // per-class cap and final output count
#define NW 7         // ceil(200/32) words for keep/suppress bitmasks

typedef unsigned long long u64;

// ---------------- device scratch (allocation-free rule: __device__ globals) ----------------
// Counters start zeroed (static init) and are re-zeroed by their consumer kernel each run,
// so every graph replay sees clean state without a dedicated zeroing launch.
__device__ int   g_cnt[Bq * Cq];                        // per-(b,c) candidate counts
__device__ float g_cscore[(size_t)Bq * Cq * MAXPC];     // per-(b,c) candidate scores
__device__ int   g_cidx[(size_t)Bq * Cq * MAXPC];       // per-(b,c) candidate roi indices
__device__ int   g_kcnt[Bq];                            // per-image kept counts
__device__ float g_kscore[Bq * MAXPC];
__device__ float g_kbox[Bq * MAXPC * 4];
__device__ int   g_ktag[Bq * MAXPC];                    // tag = class*4096 + roi_idx (<2^19)

// ---------------- kernel 1: streaming threshold filter (no argmax needed!) ----------------
// Softmax rows sum to 1 => at most one element per row exceeds 0.5, and if p > 0.5 it IS
// the row argmax. The reference emits a candidate iff p > 0.5 and class != 0 (background
// argmax is zeroed, and only scores > 0.5 survive NMS validity + final top-k zeroing).
// So we need no reduction at all: a flat, fully-coalesced float4 predicate scan.
__device__ __forceinline__ void emit_candidate(size_t e, float v) {
    int c = (int)(e % Cq);
    if (c == 0) return;                       // background
    size_t bn = e / Cq;
    int b = (int)(bn >> 12), n = (int)(bn & (Nq - 1));
    int bc = b * Cq + c;
    int pos = atomicAdd(&g_cnt[bc], 1);
    if (pos < MAXPC) {
        g_cscore[(size_t)bc * MAXPC + pos] = v;
        g_cidx[(size_t)bc * MAXPC + pos]   = n;
    }
}

__global__ void __launch_bounds__(256) filter_emit_kernel(const float4* __restrict__ probs4) {
    const int V = Bq * Nq * Cq / 4;           // 1327104 float4s (divisible by 4)
    int stride = gridDim.x * blockDim.x;
    for (int i = blockIdx.x * blockDim.x + threadIdx.x; i < V; i += stride) {
        float4 p = __ldg(&probs4[i]);
        // rare branch (~0.4% of elements pass)
        if (p.x > 0.5f) emit_candidate((size_t)i * 4 + 0, p.x);
        if (p.y > 0.5f) emit_candidate((size_t)i * 4 + 1, p.y);
        if (p.z > 0.5f) emit_candidate((size_t)i * 4 + 2, p.z);
        if (p.w > 0.5f) emit_candidate((size_t)i * 4 + 3, p.w);
    }
}

// ---------------- kernel 2: per-(b,c) sort + cap-200 + bitmask greedy NMS ----------------
__global__ void per_class_nms_kernel(const float* __restrict__ roi,
                                     const float* __restrict__ deltas) {
    __shared__ u64 skey[MAXPC];                    // 32 KB
    __shared__ float sbox[KK * 4];
    __shared__ unsigned smask[KK * NW];            // suppression bit-matrix: row i = boxes i kills
    __shared__ unsigned skeep[NW];                 // final keep mask
    __shared__ int   s_base;

    int bc = blockIdx.x;
    int b = bc / Cq, c = bc % Cq;
    int M = g_cnt[bc];                             // every thread reads M before it is re-zeroed
    if (M > MAXPC) M = MAXPC;
    if (M == 0) return;                            // counter already 0, nothing to reset

    int S = 32;
    while (S < M) S <<= 1;

    // key: score bits desc, tie -> lower roi index first (matches lax.top_k stability)
    for (int i = threadIdx.x; i < S; i += blockDim.x) {
        u64 key = 0ull;
        if (i < M) {
            float sc = g_cscore[(size_t)bc * MAXPC + i];
            int   idx = g_cidx[(size_t)bc * MAXPC + i];
            key = ((u64)__float_as_uint(sc) << 32) | (unsigned)(Nq - 1 - idx);
        }
        skey[i] = key;
    }
    __syncthreads();
    if (threadIdx.x == 0) g_cnt[bc] = 0;           // reset for next graph replay (post-barrier)

    for (int k = 2; k <= S; k <<= 1) {
        for (int j = k >> 1; j > 0; j >>= 1) {
            for (int i = threadIdx.x; i < S; i += blockDim.x) {
                int ixj = i ^ j;
                if (ixj > i) {
                    u64 a = skey[i], bv = skey[ixj];
                    bool sw = ((i & k) == 0) ? (a < bv) : (a > bv);
                    if (sw) { skey[i] = bv; skey[ixj] = a; }
                }
            }
            __syncthreads();
        }
    }

    int M2 = (M < KK) ? M : KK;   // reference per-class top-K cap

    // decode boxes for the capped candidate set; zero the bitmask rows
    for (int t = threadIdx.x; t < M2 * NW; t += blockDim.x) smask[t] = 0u;
    for (int t = threadIdx.x; t < M2; t += blockDim.x) {
        int idx = Nq - 1 - (int)(skey[t] & 0xFFFFFFFFull);
        const float* r = roi + ((size_t)b * Nq + idx) * 4;
        float y1 = r[0], x1 = r[1], y2 = r[2], x2 = r[3];
        float ah = y2 - y1, aw = x2 - x1;
        float acy = y1 + 0.5f * ah, acx = x1 + 0.5f * aw;
        const float* d = deltas + (((size_t)b * Nq + idx) * Cq + c) * 4;
        float dy = d[0] * 0.1f, dx = d[1] * 0.1f;
        float dh = d[2] * 0.2f, dw = d[3] * 0.2f;
        float bh = expf(dh) * ah, bw = expf(dw) * aw;
        float bcy = dy * ah + acy, bcx = dx * aw + acx;
        float oy1 = bcy - 0.5f * bh, ox1 = bcx - 0.5f * bw;
        sbox[t * 4 + 0] = oy1;
        sbox[t * 4 + 1] = ox1;
        sbox[t * 4 + 2] = oy1 + bh;
        sbox[t * 4 + 3] = ox1 + bw;
    }
    __syncthreads();

    // parallel IoU bit-matrix over all (i,j>i) pairs — no serial sync loop
    int npairs = M2 * M2;
    for (int t = threadIdx.x; t < npairs; t += blockDim.x) {
        int i = t / M2, j = t % M2;
        if (j > i) {
            float iy1 = sbox[i * 4 + 0], ix1 = sbox[i * 4 + 1];
            float iy2 = sbox[i * 4 + 2], ix2 = sbox[i * 4 + 3];
            float jy1 = sbox[j * 4 + 0], jx1 = sbox[j * 4 + 1];
            float jy2 = sbox[j * 4 + 2], jx2 = sbox[j * 4 + 3];
            float yy1 = fmaxf(iy1, jy1), xx1 = fmaxf(ix1, jx1);
            float yy2 = fminf(iy2, jy2), xx2 = fminf(ix2, jx2);
            float inter = fmaxf(yy2 - yy1, 0.0f) * fmaxf(xx2 - xx1, 0.0f);
            float ia = fmaxf(iy2 - iy1, 0.0f) * fmaxf(ix2 - ix1, 0.0f);
            float ja = fmaxf(jy2 - jy1, 0.0f) * fmaxf(jx2 - jx1, 0.0f);
            float iou = inter / (ia + ja - inter + 1e-8f);
            if (iou > 0.5f)
                atomicOr(&smask[i * NW + (j >> 5)], 1u << (j & 31));
        }
    }
    __syncthreads();

    // greedy scan in ONE warp: keep mask lives in lanes 0..NW-1, decision bit via shfl
    if (threadIdx.x < 32) {
        int w = threadIdx.x;                     // lane == word index (lanes >= NW idle)
        unsigned kw = 0u;
        if (w < NW) {
            int lo = w * 32;
            int nb = M2 - lo;
            kw = (nb >= 32) ? 0xFFFFFFFFu : (nb <= 0 ? 0u : ((1u << nb) - 1u));
        }
        for (int i = 0; i < M2; i++) {
            unsigned ow = __shfl_sync(0xffffffffu, kw, i >> 5);
            if ((ow >> (i & 31)) & 1u) {
                if (w < NW) kw &= ~smask[i * NW + w];   // rows only contain bits j>i
            }
        }
        if (w < NW) skeep[w] = kw;
    }
    __syncthreads();

    // popcount-based compaction into the per-image list
    if (threadIdx.x == 0) {
        int nk = 0;
        for (int w = 0; w < NW; w++) nk += __popc(skeep[w]);
        s_base = atomicAdd(&g_kcnt[b], nk);
    }
    __syncthreads();
    int base = s_base;
    for (int t = threadIdx.x; t < M2; t += blockDim.x) {
        int tw = t >> 5, tb = t & 31;
        if ((skeep[tw] >> tb) & 1u) {
            int pos = 0;
            for (int w = 0; w < tw; w++) pos += __popc(skeep[w]);
            pos += __popc(skeep[tw] & ((tb == 0) ? 0u : ((1u << tb) - 1u)));
            int o = base + pos;
            u64 key = skey[t];
            int idx = Nq - 1 - (int)(key & 0xFFFFFFFFull);
            g_kscore[b * MAXPC + o] = __uint_as_float((unsigned)(key >> 32));
            g_ktag[b * MAXPC + o]   = c * Nq + idx;
            g_kbox[(b * MAXPC + o) * 4 + 0] = sbox[t * 4 + 0];
            g_kbox[(b * MAXPC + o) * 4 + 1] = sbox[t * 4 + 1];
            g_kbox[(b * MAXPC + o) * 4 + 2] = sbox[t * 4 + 2];
            g_kbox[(b * MAXPC + o) * 4 + 3] = sbox[t * 4 + 3];
        }
    }
}

// ---------------- kernel 3: per-image top-200 via radix-bucket select + small sort ----------------
// Scores of survivors are all in (0.5, 1.0) -> fp32 exponent is constant, so mantissa bits
// are monotone in score. 256-bucket histogram finds the 200th-largest's bucket; only keys
// in buckets >= that one are compacted and bitonic-sorted (typically a few hundred, not 4096).
__device__ __forceinline__ int score_bucket(unsigned bits) {
    unsigned d = bits - 0x3F000000u;     // (0, 0x800000] for scores in (0.5, 1.0]
    int bk = (int)(d >> 15);
    return bk > 255 ? 255 : bk;
}

__global__ void finalize_kernel(float* __restrict__ out) {
    __shared__ u64 skey[MAXPC];   // 32 KB (worst case all keys in one bucket)
    __shared__ int hist[256];
    __shared__ int s_cnt, s_bsel;

    int b = blockIdx.x;
    int Mi = g_kcnt[b];
    if (Mi > MAXPC) Mi = MAXPC;

    for (int i = threadIdx.x; i < 256; i += blockDim.x) hist[i] = 0;
    if (threadIdx.x == 0) { s_cnt = 0; g_kcnt[b] = 0; }   // reset for next graph replay
    __syncthreads();

    // pass 1: histogram of score buckets
    for (int i = threadIdx.x; i < Mi; i += blockDim.x) {
        unsigned bits = __float_as_uint(g_kscore[b * MAXPC + i]);
        atomicAdd(&hist[score_bucket(bits)], 1);
    }
    __syncthreads();

    // suffix scan from the top bucket: find bucket of the target-th largest score
    if (threadIdx.x == 0) {
        int target = Mi < KK ? Mi : KK;
        int cum = 0, bsel = 0;
        for (int bk = 255; bk >= 0; bk--) {
            cum += hist[bk];
            if (cum >= target) { bsel = bk; break; }
        }
        s_bsel = bsel;
    }
    __syncthreads();
    int bsel = s_bsel;

    // pass 2: compact candidate keys (score desc; tie -> class asc, roi asc via inverted tag;
    // low 12 bits carry the storage slot as payload)
    for (int i = threadIdx.x; i < Mi; i += blockDim.x) {
        unsigned bits = __float_as_uint(g_kscore[b * MAXPC + i]);
        if (score_bucket(bits) >= bsel) {
            int pos = atomicAdd(&s_cnt, 1);
            int tag = g_ktag[b * MAXPC + i];            // < 2^19
            skey[pos] = ((u64)bits << 32) |
                        ((u64)((0xFFFFFu - (unsigned)tag) & 0xFFFFFu) << 12) |
                        (u64)(unsigned)i;
        }
    }
    __syncthreads();
    int cnt = s_cnt;

    int S = 0;
    if (cnt > 0) { S = 32; while (S < cnt) S <<= 1; }
    for (int i = cnt + threadIdx.x; i < S; i += blockDim.x) skey[i] = 0ull;
    __syncthreads();

    // bitonic sort, descending (small S: usually 256-512)
    for (int k = 2; k <= S; k <<= 1) {
        for (int j = k >> 1; j > 0; j >>= 1) {
            for (int i = threadIdx.x; i < S; i += blockDim.x) {
                int ixj = i ^ j;
                if (ixj > i) {
                    u64 a = skey[i], bv = skey[ixj];
                    bool sw = ((i & k) == 0) ? (a < bv) : (a > bv);
                    if (sw) { skey[i] = bv; skey[ixj] = a; }
                }
            }
            __syncthreads();
        }
    }

    // write top-200 (boxes, labels, scores), zero-padding: covers 100% of d_out
    int vlim = cnt < KK ? cnt : KK;                 // == min(KK, Mi) since cnt >= min(KK, Mi)
    for (int t = threadIdx.x; t < KK; t += blockDim.x) {
        float bx0 = 0.f, bx1 = 0.f, bx2 = 0.f, bx3 = 0.f, lbl = 0.f, scv = 0.f;
        if (t < vlim) {
            u64 key = skey[t];
            scv = __uint_as_float((unsigned)(key >> 32));   // always > 0.5 here
            int slot = (int)(key & 0xFFFull);
            int tag = 0xFFFFF - (int)((key >> 12) & 0xFFFFFull);
            lbl = (float)(tag >> 12);                       // tag / 4096 = class
            const float* bp = &g_kbox[(b * MAXPC + slot) * 4];
            bx0 = fminf(fmaxf(bp[0], 0.0f), 1.0f);
            bx1 = fminf(fmaxf(bp[1], 0.0f), 1.0f);
            bx2 = fminf(fmaxf(bp[2], 0.0f), 1.0f);
            bx3 = fminf(fmaxf(bp[3], 0.0f), 1.0f);
        }
        float* ob = out + ((size_t)b * KK + t) * 4;
        ob[0] = bx0; ob[1] = bx1; ob[2] = bx2; ob[3] = bx3;
        out[(size_t)Bq * KK * 4 + (size_t)b * KK + t] = lbl;
        out[(size_t)Bq * KK * 4 + (size_t)Bq * KK + (size_t)b * KK + t] = scv;
    }
}

// ---------------- host launch ----------------
extern "C" void kernel_launch(void* const* d_in, const int* in_sizes, int n_in,
                              void* d_out, int out_size) {
    const float* roi = nullptr;     // B*N*4       = 262144
    const float* deltas = nullptr;  // B*N*C*4     = 21233664
    const float* probs = nullptr;   // B*N*C       = 5308416
    for (int i = 0; i < n_in; i++) {
        if (in_sizes[i] == Bq * Nq * 4)           roi    = (const float*)d_in[i];
        else if (in_sizes[i] == Bq * Nq * Cq * 4) deltas = (const float*)d_in[i];
        else if (in_sizes[i] == Bq * Nq * Cq)     probs  = (const float*)d_in[i];
    }
    float* out = (float*)d_out;

    // 8 blocks per SM worth of threads, grid-stride over 1.3M float4s
    filter_emit_kernel<<<1184, 256>>>((const float4*)probs);
    per_class_nms_kernel<<<Bq * Cq, 256>>>(roi, deltas);
    finalize_kernel<<<Bq, 1024>>>(out);
}